// round 15
// baseline (speedup 1.0000x reference)
#include <cuda_runtime.h>
#include <cuda_fp16.h>
#include <math.h>

#define NSEQ  4096
#define DIMM  1024
#define HEADS 16
#define HD    64
#define WIDTH 512
#define NW    8
#define NST   512
#define KEYW  1024

// ---------------- scratch ----------------
__device__ float g_xn[NSEQ*DIMM];
__device__ float g_qkv[NSEQ*3*DIMM];
__device__ float g_q2s[NSEQ*DIMM];
__device__ float g_state_qkv[NST*3*DIMM];
__device__ float g_st[NST*DIMM];
__device__ float g_qfs_raw[NST*DIMM];

__device__ float g_qn_main[HEADS*NSEQ*HD];
__device__ float g_kn_main[HEADS*NSEQ*HD];
__device__ float g_qn_ts[HEADS*NSEQ*HD];
__device__ float g_kn_ts[HEADS*NST*HD];
__device__ float g_qn_ss[HEADS*NST*HD];
__device__ float g_kn_ss[HEADS*NST*HD];
__device__ float g_qn_fs[HEADS*NST*HD];
__device__ float g_kn_fs[HEADS*NST*HD];

__device__ float g_cat[NSEQ*2*DIMM];
__device__ float g_state_cat[NST*2*DIMM];
__device__ float g_so[NST*DIMM];
__device__ float g_z[NST*DIMM];

// ---------------- layernorm ----------------
__global__ void __launch_bounds__(256) ln_kernel(const float* __restrict__ x,
        const float* __restrict__ gamma, const float* __restrict__ pos,
        float* __restrict__ out)
{
    int row = blockIdx.x;
    const float* xr = x + (long)row*DIMM;
    float* orow = out + (long)row*DIMM;
    __shared__ float red[256];
    float s = 0.f, s2 = 0.f;
    for (int i = threadIdx.x; i < DIMM; i += 256) { float v = xr[i]; s += v; s2 += v*v; }
    red[threadIdx.x] = s; __syncthreads();
    for (int o = 128; o; o >>= 1) { if (threadIdx.x < o) red[threadIdx.x] += red[threadIdx.x+o]; __syncthreads(); }
    float mu = red[0] * (1.f/DIMM);
    __syncthreads();
    red[threadIdx.x] = s2; __syncthreads();
    for (int o = 128; o; o >>= 1) { if (threadIdx.x < o) red[threadIdx.x] += red[threadIdx.x+o]; __syncthreads(); }
    float var = red[0] * (1.f/DIMM) - mu*mu;
    float inv = rsqrtf(var + 1e-5f);
    for (int i = threadIdx.x; i < DIMM; i += 256) {
        float v = (xr[i]-mu)*inv*gamma[i];
        if (pos) v += pos[(long)row*DIMM + i];
        orow[i] = v;
    }
}

// ---------------- TF32 helpers ----------------
__device__ __forceinline__ unsigned f2tf32(float f)
{
    unsigned r;
    asm("cvt.rna.tf32.f32 %0, %1;" : "=r"(r) : "f"(f));
    return r;
}

__device__ __forceinline__ void mma_tf32(float c[4], const unsigned a[4], const unsigned b[2])
{
    asm volatile(
        "mma.sync.aligned.m16n8k8.row.col.f32.tf32.tf32.f32 "
        "{%0,%1,%2,%3}, {%4,%5,%6,%7}, {%8,%9}, {%0,%1,%2,%3};"
        : "+f"(c[0]), "+f"(c[1]), "+f"(c[2]), "+f"(c[3])
        : "r"(a[0]), "r"(a[1]), "r"(a[2]), "r"(a[3]), "r"(b[0]), "r"(b[1]));
}

__device__ __forceinline__ void cp16(float* dst, const float* src)
{
    unsigned d = (unsigned)__cvta_generic_to_shared(dst);
    asm volatile("cp.async.cg.shared.global [%0], [%1], 16;" :: "r"(d), "l"(src));
}

__device__ __forceinline__ void cp16p(float* dst, const float* src, int sz)
{
    unsigned d = (unsigned)__cvta_generic_to_shared(dst);
    asm volatile("cp.async.cg.shared.global [%0], [%1], 16, %2;" :: "r"(d), "l"(src), "r"(sz));
}

// ---------------- TF32 GEMM: cp.async 4-stage pipeline ----------------
#define TG_STAGES 4
#define TG_ASTRIDE 20
#define TG_ATILE (128*TG_ASTRIDE)
#define TG_BTILE (16*132)
#define TGEMM_SMEM (TG_STAGES*(TG_ATILE + TG_BTILE)*4)

__global__ void __launch_bounds__(256) tgemm(const float* __restrict__ A,
        const float* __restrict__ B, float* __restrict__ C,
        int M, int N, int K, int accum)
{
    extern __shared__ float tsm[];
    float* Asm = tsm;
    float* Bsm = tsm + TG_STAGES*TG_ATILE;

    int tid = threadIdx.x;
    int warp = tid >> 5, lane = tid & 31;
    int wy = warp >> 1, wx = warp & 1;
    int g = lane >> 2, t4 = lane & 3;
    int m0 = blockIdx.y*128, n0 = blockIdx.x*128;

    int nkt = K >> 4;

    auto issue = [&](int kt) {
        int buf = kt & (TG_STAGES-1);
        float* as = Asm + buf*TG_ATILE;
        float* bs = Bsm + buf*TG_BTILE;
        int row = tid >> 2, seg = (tid & 3)*4;
        const float* a0 = A + (long)(m0 + row)*K + kt*16 + seg;
        cp16(as + row*TG_ASTRIDE + seg, a0);
        cp16(as + (row+64)*TG_ASTRIDE + seg, a0 + (long)64*K);
        int krow = tid >> 5, col = (tid & 31)*4;
        const float* b0 = B + (long)(kt*16 + krow)*N + n0 + col;
        cp16(bs + krow*132 + col, b0);
        cp16(bs + (krow+8)*132 + col, b0 + (long)8*N);
        asm volatile("cp.async.commit_group;");
    };

    float acc[2][8][4];
    #pragma unroll
    for (int mi = 0; mi < 2; mi++)
        #pragma unroll
        for (int nj = 0; nj < 8; nj++)
            #pragma unroll
            for (int c = 0; c < 4; c++) acc[mi][nj][c] = 0.f;

    #pragma unroll
    for (int s = 0; s < TG_STAGES-1; s++)
        if (s < nkt) issue(s);

    for (int kt = 0; kt < nkt; kt++) {
        asm volatile("cp.async.wait_group %0;" :: "n"(TG_STAGES-2));
        __syncthreads();

        if (kt + TG_STAGES-1 < nkt) issue(kt + TG_STAGES-1);

        int buf = kt & (TG_STAGES-1);
        const float* as = Asm + buf*TG_ATILE;
        const float* bs = Bsm + buf*TG_BTILE;

        #pragma unroll
        for (int ks = 0; ks < 2; ks++) {
            int kk = ks*8;
            unsigned af[2][4], bf[8][2];
            #pragma unroll
            for (int mi = 0; mi < 2; mi++) {
                int mr = wy*32 + mi*16 + g;
                af[mi][0] = f2tf32(as[mr*TG_ASTRIDE + kk + t4]);
                af[mi][1] = f2tf32(as[(mr+8)*TG_ASTRIDE + kk + t4]);
                af[mi][2] = f2tf32(as[mr*TG_ASTRIDE + kk + t4 + 4]);
                af[mi][3] = f2tf32(as[(mr+8)*TG_ASTRIDE + kk + t4 + 4]);
            }
            #pragma unroll
            for (int nj = 0; nj < 8; nj++) {
                int nc = wx*64 + nj*8 + g;
                bf[nj][0] = f2tf32(bs[(kk + t4)*132 + nc]);
                bf[nj][1] = f2tf32(bs[(kk + t4 + 4)*132 + nc]);
            }
            #pragma unroll
            for (int mi = 0; mi < 2; mi++)
                #pragma unroll
                for (int nj = 0; nj < 8; nj++)
                    mma_tf32(acc[mi][nj], af[mi], bf[nj]);
        }
    }

    #pragma unroll
    for (int mi = 0; mi < 2; mi++) {
        #pragma unroll
        for (int nj = 0; nj < 8; nj++) {
            int row = m0 + wy*32 + mi*16 + g;
            int col = n0 + wx*64 + nj*8 + t4*2;
            float* p0 = &C[(long)row*N + col];
            float* p1 = &C[(long)(row+8)*N + col];
            float2 v0 = make_float2(acc[mi][nj][0], acc[mi][nj][1]);
            float2 v1 = make_float2(acc[mi][nj][2], acc[mi][nj][3]);
            if (accum) {
                float2 o0 = *(float2*)p0, o1 = *(float2*)p1;
                v0.x += o0.x; v0.y += o0.y; v1.x += o1.x; v1.y += o1.y;
            }
            *(float2*)p0 = v0;
            *(float2*)p1 = v1;
        }
    }
}

// ---------------- l2norm + scale: warp per (row,head), float2 per lane ----------------
__global__ void __launch_bounds__(256) norm_heads(const float* __restrict__ src,
        int srcStride, int colOff, int rowOff,
        const float* __restrict__ scale, float* __restrict__ dst, int nrows)
{
    int w = threadIdx.x >> 5, lane = threadIdx.x & 31;
    int pair = blockIdx.x*8 + w;
    int h = pair / nrows;
    int row = pair - h*nrows;
    int d0 = lane*2;

    const float* sp = src + (long)(rowOff+row)*srcStride + colOff + h*HD + d0;
    float2 v = *(const float2*)sp;
    float s = v.x*v.x + v.y*v.y;
    #pragma unroll
    for (int o = 16; o; o >>= 1) s += __shfl_xor_sync(0xffffffffu, s, o);
    float inv = 1.f / fmaxf(sqrtf(s), 1e-12f);
    float2 sc = *(const float2*)(scale + d0);
    float2 r = make_float2(v.x*inv*sc.x, v.y*inv*sc.y);
    *(float2*)(dst + (long)pair*HD + d0) = r;
}

// ---------------- flash attention: cp.async K/V raw, f16x2 exp2 softmax ----------------
#define FPAD 68
#define TILEU (64*FPAD)
#define FLASH_SMEM (6*TILEU*4 + 256*4)
#define L2E 1.4426950408889634f

__global__ void __launch_bounds__(256, 2) flashmma(
        const float* __restrict__ Q, int qHeadRows,
        const float* __restrict__ Kh, int kHeadRows,
        const float* __restrict__ Vall, long vstride, int vColHeadMul, int vColAdd,
        int vRowExtra,
        const float* __restrict__ bias,
        float* __restrict__ Out, long ostride, int oColMul, int oColAdd,
        int L, int nwin)
{
    extern __shared__ unsigned usm[];
    unsigned* QHI = usm;
    unsigned* QLO = usm + TILEU;
    float* KR  = (float*)(usm + 2*TILEU);
    float* VR0 = (float*)(usm + 3*TILEU);
    float* VR1 = (float*)(usm + 4*TILEU);
    unsigned* PT = usm + 5*TILEU;
    float* SMAX = (float*)(usm + 6*TILEU);
    float* SSUM = SMAX + 128;

    int tid = threadIdx.x;
    int warp = tid >> 5, lane = tid & 31;
    int wy = warp >> 1, wx = warp & 1;
    int g = lane >> 2, t4 = lane & 3;

    int z = blockIdx.y;
    int h = z / nwin, w = z - h*nwin;
    int winw = qHeadRows / nwin;
    int i0 = blockIdx.x*64;
    int qrow0 = w*winw + i0;
    int kOff = (nwin > 1) ? (w-1)*winw : 0;

    const float* Qblk = Q + ((long)h*qHeadRows + qrow0)*64;
    const float* Kbase = Kh + (long)h*kHeadRows*64;
    const float* Vbase = Vall + vColHeadMul*h + vColAdd;
    const float* biasH = bias ? bias + (long)h*WIDTH*KEYW : nullptr;

    auto issueK = [&](int c0) {
        #pragma unroll
        for (int t = 0; t < 4; t++) {
            int c4 = tid + t*256;
            int key = c4 >> 4, seg = (c4 & 15)*4;
            int kr = kOff + c0 + key;
            cp16p(KR + key*FPAD + seg, Kbase + (long)kr*64 + seg, (kr >= 0) ? 16 : 0);
        }
        asm volatile("cp.async.commit_group;");
    };
    auto issueV = [&](int c0, float* VB) {
        #pragma unroll
        for (int t = 0; t < 4; t++) {
            int c4 = tid + t*256;
            int key = c4 >> 4, seg = (c4 & 15)*4;
            int kr = kOff + c0 + key;
            cp16p(VB + key*FPAD + seg, Vbase + (long)(kr + vRowExtra)*vstride + seg,
                  (kr >= 0) ? 16 : 0);
        }
        asm volatile("cp.async.commit_group;");
    };

    #pragma unroll
    for (int t = 0; t < 16; t++) {
        int e = tid + t*256;
        int r = e >> 6, c = e & 63;
        float v = Qblk[(long)r*64 + c];
        unsigned hi = f2tf32(v);
        QHI[c*FPAD + r] = hi;
        QLO[c*FPAD + r] = f2tf32(v - __uint_as_float(hi));
    }

    int mr = wy*16 + g;
    float m0r = -3.402823466e38f, m1r = -3.402823466e38f;
    float l0 = 0.f, l1 = 0.f;
    float acc[4][4];
    #pragma unroll
    for (int nj = 0; nj < 4; nj++)
        #pragma unroll
        for (int c = 0; c < 4; c++) acc[nj][c] = 0.f;

    int Lq = biasH ? (i0 + 576) : L;
    if (Lq > L) Lq = L;
    int nch = (Lq + 63) >> 6;

    issueV(0, VR0);
    issueK(0);

    for (int ci = 0; ci < nch; ci++) {
        int c0 = ci << 6;
        float* VB = (ci & 1) ? VR1 : VR0;
        bool more = (ci + 1 < nch);

        if (more) {
            issueV(c0 + 64, (ci & 1) ? VR0 : VR1);
            asm volatile("cp.async.wait_group 1;");
        } else {
            asm volatile("cp.async.wait_group 0;");
        }
        __syncthreads();

        float sf[4][4];
        #pragma unroll
        for (int nj = 0; nj < 4; nj++)
            #pragma unroll
            for (int c = 0; c < 4; c++) sf[nj][c] = 0.f;

        #pragma unroll
        for (int kk = 0; kk < 64; kk += 8) {
            unsigned ahi[4], alo[4];
            ahi[0] = QHI[(kk+t4)*FPAD + mr];
            ahi[1] = QHI[(kk+t4)*FPAD + mr + 8];
            ahi[2] = QHI[(kk+t4+4)*FPAD + mr];
            ahi[3] = QHI[(kk+t4+4)*FPAD + mr + 8];
            alo[0] = QLO[(kk+t4)*FPAD + mr];
            alo[1] = QLO[(kk+t4)*FPAD + mr + 8];
            alo[2] = QLO[(kk+t4+4)*FPAD + mr];
            alo[3] = QLO[(kk+t4+4)*FPAD + mr + 8];
            #pragma unroll
            for (int nj = 0; nj < 4; nj++) {
                int nc = wx*32 + nj*8 + g;
                float k0 = KR[nc*FPAD + kk + t4];
                float k1 = KR[nc*FPAD + kk + t4 + 4];
                unsigned bhi[2] = { f2tf32(k0), f2tf32(k1) };
                unsigned blo[2] = { f2tf32(k0 - __uint_as_float(bhi[0])),
                                    f2tf32(k1 - __uint_as_float(bhi[1])) };
                mma_tf32(sf[nj], ahi, bhi);
                mma_tf32(sf[nj], alo, bhi);
                mma_tf32(sf[nj], ahi, blo);
            }
        }

        int ir0 = i0 + mr, ir1 = ir0 + 8;
        #pragma unroll
        for (int nj = 0; nj < 4; nj++) {
            int j0 = c0 + wx*32 + nj*8 + 2*t4;
            #pragma unroll
            for (int c = 0; c < 4; c++) sf[nj][c] *= 8.f;
            if (biasH) {
                float2 b0 = *(const float2*)&biasH[(long)ir0*KEYW + j0];
                float2 b1 = *(const float2*)&biasH[(long)ir1*KEYW + j0];
                sf[nj][0] += b0.x; sf[nj][1] += b0.y;
                sf[nj][2] += b1.x; sf[nj][3] += b1.y;
                if (j0     > ir0 + 512) sf[nj][0] = -3.402823466e38f;
                if (j0 + 1 > ir0 + 512) sf[nj][1] = -3.402823466e38f;
                if (j0     > ir1 + 512) sf[nj][2] = -3.402823466e38f;
                if (j0 + 1 > ir1 + 512) sf[nj][3] = -3.402823466e38f;
            }
        }

        float pm0 = -3.402823466e38f, pm1 = -3.402823466e38f;
        #pragma unroll
        for (int nj = 0; nj < 4; nj++) {
            pm0 = fmaxf(pm0, fmaxf(sf[nj][0], sf[nj][1]));
            pm1 = fmaxf(pm1, fmaxf(sf[nj][2], sf[nj][3]));
        }
        pm0 = fmaxf(pm0, __shfl_xor_sync(0xffffffffu, pm0, 1));
        pm0 = fmaxf(pm0, __shfl_xor_sync(0xffffffffu, pm0, 2));
        pm1 = fmaxf(pm1, __shfl_xor_sync(0xffffffffu, pm1, 1));
        pm1 = fmaxf(pm1, __shfl_xor_sync(0xffffffffu, pm1, 2));
        if (t4 == 0) {
            SMAX[mr*2 + wx] = pm0;
            SMAX[(mr+8)*2 + wx] = pm1;
        }
        __syncthreads();

        if (more) issueK(c0 + 64);

        float cmax0 = fmaxf(SMAX[mr*2], SMAX[mr*2+1]);
        float cmax1 = fmaxf(SMAX[(mr+8)*2], SMAX[(mr+8)*2+1]);

        float mn0 = fmaxf(m0r, cmax0);
        float mn1 = fmaxf(m1r, cmax1);
        float corr0 = __expf(m0r - mn0);
        float corr1 = __expf(m1r - mn1);
        m0r = mn0; m1r = mn1;

        // exp via f16x2 EX2 (2 entries per MUFU op); widen to f32 for sums + tf32 P
        float mnl0 = mn0*L2E, mnl1 = mn1*L2E;
        float ps0 = 0.f, ps1 = 0.f;
        #pragma unroll
        for (int nj = 0; nj < 4; nj++) {
            int j0 = wx*32 + nj*8 + 2*t4;
            __half2 t0 = __floats2half2_rn(__fmaf_rn(sf[nj][0], L2E, -mnl0),
                                           __fmaf_rn(sf[nj][1], L2E, -mnl0));
            __half2 t1 = __floats2half2_rn(__fmaf_rn(sf[nj][2], L2E, -mnl1),
                                           __fmaf_rn(sf[nj][3], L2E, -mnl1));
            t0 = h2exp2(t0);
            t1 = h2exp2(t1);
            float2 p0 = __half22float2(t0);
            float2 p1 = __half22float2(t1);
            ps0 += p0.x + p0.y;
            ps1 += p1.x + p1.y;
            PT[j0*FPAD + mr]       = f2tf32(p0.x);
            PT[(j0+1)*FPAD + mr]   = f2tf32(p0.y);
            PT[j0*FPAD + mr+8]     = f2tf32(p1.x);
            PT[(j0+1)*FPAD + mr+8] = f2tf32(p1.y);
        }
        ps0 += __shfl_xor_sync(0xffffffffu, ps0, 1);
        ps0 += __shfl_xor_sync(0xffffffffu, ps0, 2);
        ps1 += __shfl_xor_sync(0xffffffffu, ps1, 1);
        ps1 += __shfl_xor_sync(0xffffffffu, ps1, 2);
        if (t4 == 0) {
            SSUM[mr*2 + wx] = ps0;
            SSUM[(mr+8)*2 + wx] = ps1;
        }

        #pragma unroll
        for (int nj = 0; nj < 4; nj++) {
            acc[nj][0] *= corr0; acc[nj][1] *= corr0;
            acc[nj][2] *= corr1; acc[nj][3] *= corr1;
        }
        __syncthreads();

        l0 = l0*corr0 + SSUM[mr*2] + SSUM[mr*2+1];
        l1 = l1*corr1 + SSUM[(mr+8)*2] + SSUM[(mr+8)*2+1];

        #pragma unroll
        for (int kk = 0; kk < 64; kk += 8) {
            unsigned ap[4];
            ap[0] = PT[(kk+t4)*FPAD + mr];
            ap[1] = PT[(kk+t4)*FPAD + mr + 8];
            ap[2] = PT[(kk+t4+4)*FPAD + mr];
            ap[3] = PT[(kk+t4+4)*FPAD + mr + 8];
            #pragma unroll
            for (int nj = 0; nj < 4; nj++) {
                int nc = wx*32 + nj*8 + g;
                unsigned bv[2] = { f2tf32(VB[(kk+t4)*FPAD + nc]),
                                   f2tf32(VB[(kk+t4+4)*FPAD + nc]) };
                mma_tf32(acc[nj], ap, bv);
            }
        }
        __syncthreads();
    }

    float inv0 = 1.f / l0, inv1 = 1.f / l1;
    #pragma unroll
    for (int nj = 0; nj < 4; nj++) {
        int col = h*oColMul + oColAdd + wx*32 + nj*8 + 2*t4;
        long r0 = (long)(qrow0 + mr)*ostride + col;
        long r1 = (long)(qrow0 + mr + 8)*ostride + col;
        *(float2*)&Out[r0] = make_float2(acc[nj][0]*inv0, acc[nj][1]*inv0);
        *(float2*)&Out[r1] = make_float2(acc[nj][2]*inv1, acc[nj][3]*inv1);
    }
}

// ---------------- memories copy ----------------
__global__ void memories_kernel(const float* __restrict__ qkv, float* __restrict__ out)
{
    int idx = blockIdx.x*256 + threadIdx.x;
    if (idx >= 2*HEADS*WIDTH*HD) return;
    int d = idx & 63;
    int i = (idx >> 6) & 511;
    int h = (idx >> 15) & 15;
    int s = idx >> 19;
    out[idx] = qkv[(long)(3584+i)*3072 + (s ? 2048 : 1024) + h*HD + d];
}

// ---------------- new_states ----------------
__global__ void newstates_kernel(const float* __restrict__ gz, const float* __restrict__ bg,
        const float* __restrict__ beta, const float* __restrict__ init_state,
        float* __restrict__ out)
{
    int idx = blockIdx.x*256 + threadIdx.x;
    if (idx >= NST*DIMM) return;
    int c = idx & (DIMM-1);
    float sig = 1.f/(1.f+expf(-beta[c]));
    float z = gz[idx] + bg[c];
    out[idx] = sig*z + (1.f-sig)*init_state[idx];
}

// ---------------- host launch ----------------
static float* symaddr(const void* s)
{
    void* p = nullptr;
    cudaGetSymbolAddress(&p, s);
    return (float*)p;
}

extern "C" void kernel_launch(void* const* d_in, const int* in_sizes, int n_in,
                              void* d_out, int out_size)
{
    const float* x       = (const float*)d_in[0];
    const float* bias    = (const float*)d_in[1];
    const float* gamma   = (const float*)d_in[2];
    const float* w_qkv   = (const float*)d_in[3];
    const float* q_scale = (const float*)d_in[4];
    const float* k_scale = (const float*)d_in[5];
    const float* w_out   = (const float*)d_in[6];
    const float* s_gamma = (const float*)d_in[7];
    const float* w_q2s   = (const float*)d_in[8];
    const float* w_qfs   = (const float*)d_in[9];
    const float* w_sqkv  = (const float*)d_in[10];
    const float* init_st = (const float*)d_in[11];
    const float* pos_ids = (const float*)d_in[12];
    const float* w_sout  = (const float*)d_in[13];
    const float* ts_q    = (const float*)d_in[14];
    const float* ts_k    = (const float*)d_in[15];
    const float* ss_q    = (const float*)d_in[16];
    const float* ss_k    = (const float*)d_in[17];
    const float* fs_q    = (const float*)d_in[18];
    const float* fs_k    = (const float*)d_in[19];
    const float* w_gate  = (const float*)d_in[20];
    const float* b_gate  = (const float*)d_in[21];
    const float* beta    = (const float*)d_in[22];
    float* out = (float*)d_out;

    float* xn   = symaddr(g_xn);
    float* qkv  = symaddr(g_qkv);
    float* q2s  = symaddr(g_q2s);
    float* sqkv = symaddr(g_state_qkv);
    float* st   = symaddr(g_st);
    float* qfsr = symaddr(g_qfs_raw);
    float* qnm  = symaddr(g_qn_main);
    float* knm  = symaddr(g_kn_main);
    float* qnts = symaddr(g_qn_ts);
    float* knts = symaddr(g_kn_ts);
    float* qnss = symaddr(g_qn_ss);
    float* knss = symaddr(g_kn_ss);
    float* qnfs = symaddr(g_qn_fs);
    float* knfs = symaddr(g_kn_fs);
    float* cat  = symaddr(g_cat);
    float* scat = symaddr(g_state_cat);
    float* so   = symaddr(g_so);
    float* zb   = symaddr(g_z);

    static cudaStream_t s1 = nullptr;
    static cudaEvent_t evXn, evQn, evTs, evS1;
    if (!s1) {
        cudaStreamCreateWithFlags(&s1, cudaStreamNonBlocking);
        cudaEventCreateWithFlags(&evXn, cudaEventDisableTiming);
        cudaEventCreateWithFlags(&evQn, cudaEventDisableTiming);
        cudaEventCreateWithFlags(&evTs, cudaEventDisableTiming);
        cudaEventCreateWithFlags(&evS1, cudaEventDisableTiming);
        cudaFuncSetAttribute(flashmma, cudaFuncAttributeMaxDynamicSharedMemorySize, FLASH_SMEM);
        cudaFuncSetAttribute(tgemm, cudaFuncAttributeMaxDynamicSharedMemorySize, TGEMM_SMEM);
    }

    cudaStream_t s0 = 0;

    // ===== stream0: main path =====
    ln_kernel<<<NSEQ, 256, 0, s0>>>(x, gamma, nullptr, xn);
    cudaEventRecord(evXn, s0);

    tgemm<<<dim3(3072/128, NSEQ/128), 256, TGEMM_SMEM, s0>>>(xn, w_qkv, qkv, NSEQ, 3072, DIMM, 0);
    norm_heads<<<NSEQ*HEADS/8, 256, 0, s0>>>(qkv, 3072, 0,    0,    q_scale, qnm,  NSEQ);
    norm_heads<<<NSEQ*HEADS/8, 256, 0, s0>>>(qkv, 3072, 1024, 0,    k_scale, knm,  NSEQ);
    norm_heads<<<NST*HEADS/8,  256, 0, s0>>>(qkv, 3072, 1024, 3584, fs_k,    knfs, NST);
    cudaEventRecord(evQn, s0);

    flashmma<<<dim3(WIDTH/64, HEADS*NW), 256, FLASH_SMEM, s0>>>(
        qnm, NSEQ, knm, NSEQ, qkv, 3072, HD, 2048, 0, bias,
        cat, 2*DIMM, HD, 0, KEYW, NW);

    // ===== stream1: state branch =====
    cudaStreamWaitEvent(s1, evXn, 0);
    ln_kernel<<<NST, 256, 0, s1>>>(init_st, s_gamma, pos_ids, st);
    tgemm<<<dim3(3072/128, NST/128), 256, TGEMM_SMEM, s1>>>(init_st, w_sqkv, sqkv, NST, 3072, DIMM, 0);
    tgemm<<<dim3(DIMM/128, NST/128), 256, TGEMM_SMEM, s1>>>(st, w_qfs, qfsr, NST, DIMM, DIMM, 0);
    tgemm<<<dim3(DIMM/128, NSEQ/128), 256, TGEMM_SMEM, s1>>>(xn, w_q2s, q2s, NSEQ, DIMM, DIMM, 0);

    norm_heads<<<NSEQ*HEADS/8, 256, 0, s1>>>(q2s, 1024, 0,    0, ts_q, qnts, NSEQ);
    norm_heads<<<NST*HEADS/8,  256, 0, s1>>>(sqkv, 3072, 1024, 0, ts_k, knts, NST);
    norm_heads<<<NST*HEADS/8,  256, 0, s1>>>(sqkv, 3072, 0,    0, ss_q, qnss, NST);
    norm_heads<<<NST*HEADS/8,  256, 0, s1>>>(sqkv, 3072, 1024, 0, ss_k, knss, NST);
    norm_heads<<<NST*HEADS/8,  256, 0, s1>>>(qfsr, 1024, 0,    0, fs_q, qnfs, NST);

    flashmma<<<dim3(NSEQ/64, HEADS), 256, FLASH_SMEM, s1>>>(
        qnts, NSEQ, knts, NST, sqkv, 3072, HD, 2048, 0, nullptr,
        cat, 2*DIMM, HD, DIMM, NST, 1);
    cudaEventRecord(evTs, s1);

    flashmma<<<dim3(NST/64, HEADS), 256, FLASH_SMEM, s1>>>(
        qnss, NST, knss, NST, sqkv, 3072, HD, 2048, 0, nullptr,
        scat, 2*DIMM, 2*HD, 0, NST, 1);

    cudaStreamWaitEvent(s1, evQn, 0);
    flashmma<<<dim3(NST/64, HEADS), 256, FLASH_SMEM, s1>>>(
        qnfs, NST, knfs, NST, qkv, 3072, HD, 2048, 3584, nullptr,
        scat, 2*DIMM, 2*HD, HD, NST, 1);
    memories_kernel<<<(2*HEADS*WIDTH*HD)/256, 256, 0, s1>>>(qkv, out + (long)NSEQ*DIMM);

    tgemm<<<dim3(DIMM/128, NST/128), 256, TGEMM_SMEM, s1>>>(scat, w_sout, so, NST, DIMM, 2*DIMM, 0);
    tgemm<<<dim3(DIMM/128, NST/128), 256, TGEMM_SMEM, s1>>>(so, w_gate, zb, NST, DIMM, DIMM, 0);
    newstates_kernel<<<(NST*DIMM)/256, 256, 0, s1>>>(zb, b_gate, beta, init_st,
            out + (long)NSEQ*DIMM + 2*HEADS*WIDTH*HD);
    cudaEventRecord(evS1, s1);

    // ===== stream0: output projection =====
    cudaStreamWaitEvent(s0, evTs, 0);
    tgemm<<<dim3(DIMM/128, NSEQ/128), 256, TGEMM_SMEM, s0>>>(cat, w_out, out, NSEQ, DIMM, 2*DIMM, 0);

    cudaStreamWaitEvent(s0, evS1, 0);
}

// round 16
// speedup vs baseline: 1.0691x; 1.0691x over previous
#include <cuda_runtime.h>
#include <math.h>

#define NSEQ  4096
#define DIMM  1024
#define HEADS 16
#define HD    64
#define WIDTH 512
#define NW    8
#define NST   512
#define KEYW  1024

// ---------------- scratch ----------------
__device__ float g_xn[NSEQ*DIMM];
__device__ float g_qkv[NSEQ*3*DIMM];
__device__ float g_q2s[NSEQ*DIMM];
__device__ float g_state_qkv[NST*3*DIMM];
__device__ float g_st[NST*DIMM];
__device__ float g_qfs_raw[NST*DIMM];

__device__ float g_qn_main[HEADS*NSEQ*HD];
__device__ float g_kn_main[HEADS*NSEQ*HD];
__device__ float g_qn_ts[HEADS*NSEQ*HD];
__device__ float g_kn_ts[HEADS*NST*HD];
__device__ float g_qn_ss[HEADS*NST*HD];
__device__ float g_kn_ss[HEADS*NST*HD];
__device__ float g_qn_fs[HEADS*NST*HD];
__device__ float g_kn_fs[HEADS*NST*HD];

__device__ float g_cat[NSEQ*2*DIMM];
__device__ float g_state_cat[NST*2*DIMM];
__device__ float g_so[NST*DIMM];
__device__ float g_z[NST*DIMM];

// ---------------- layernorm ----------------
__global__ void __launch_bounds__(256) ln_kernel(const float* __restrict__ x,
        const float* __restrict__ gamma, const float* __restrict__ pos,
        float* __restrict__ out)
{
    int row = blockIdx.x;
    const float* xr = x + (long)row*DIMM;
    float* orow = out + (long)row*DIMM;
    __shared__ float red[256];
    float s = 0.f, s2 = 0.f;
    for (int i = threadIdx.x; i < DIMM; i += 256) { float v = xr[i]; s += v; s2 += v*v; }
    red[threadIdx.x] = s; __syncthreads();
    for (int o = 128; o; o >>= 1) { if (threadIdx.x < o) red[threadIdx.x] += red[threadIdx.x+o]; __syncthreads(); }
    float mu = red[0] * (1.f/DIMM);
    __syncthreads();
    red[threadIdx.x] = s2; __syncthreads();
    for (int o = 128; o; o >>= 1) { if (threadIdx.x < o) red[threadIdx.x] += red[threadIdx.x+o]; __syncthreads(); }
    float var = red[0] * (1.f/DIMM) - mu*mu;
    float inv = rsqrtf(var + 1e-5f);
    for (int i = threadIdx.x; i < DIMM; i += 256) {
        float v = (xr[i]-mu)*inv*gamma[i];
        if (pos) v += pos[(long)row*DIMM + i];
        orow[i] = v;
    }
}

// ---------------- TF32 helpers ----------------
__device__ __forceinline__ unsigned f2tf32(float f)
{
    unsigned r;
    asm("cvt.rna.tf32.f32 %0, %1;" : "=r"(r) : "f"(f));
    return r;
}

__device__ __forceinline__ void mma_tf32(float c[4], const unsigned a[4], const unsigned b[2])
{
    asm volatile(
        "mma.sync.aligned.m16n8k8.row.col.f32.tf32.tf32.f32 "
        "{%0,%1,%2,%3}, {%4,%5,%6,%7}, {%8,%9}, {%0,%1,%2,%3};"
        : "+f"(c[0]), "+f"(c[1]), "+f"(c[2]), "+f"(c[3])
        : "r"(a[0]), "r"(a[1]), "r"(a[2]), "r"(a[3]), "r"(b[0]), "r"(b[1]));
}

__device__ __forceinline__ void cp16(float* dst, const float* src)
{
    unsigned d = (unsigned)__cvta_generic_to_shared(dst);
    asm volatile("cp.async.cg.shared.global [%0], [%1], 16;" :: "r"(d), "l"(src));
}

__device__ __forceinline__ void cp16p(float* dst, const float* src, int sz)
{
    unsigned d = (unsigned)__cvta_generic_to_shared(dst);
    asm volatile("cp.async.cg.shared.global [%0], [%1], 16, %2;" :: "r"(d), "l"(src), "r"(sz));
}

// ---------------- TF32 GEMM: cp.async 4-stage pipeline, conflict-free B ----------------
#define TG_STAGES 4
#define TG_ASTRIDE 20
#define TG_BSTRIDE 136
#define TG_ATILE (128*TG_ASTRIDE)
#define TG_BTILE (16*TG_BSTRIDE)
#define TGEMM_SMEM (TG_STAGES*(TG_ATILE + TG_BTILE)*4)

__global__ void __launch_bounds__(256) tgemm(const float* __restrict__ A,
        const float* __restrict__ B, float* __restrict__ C,
        int M, int N, int K, int accum)
{
    extern __shared__ float tsm[];
    float* Asm = tsm;
    float* Bsm = tsm + TG_STAGES*TG_ATILE;

    int tid = threadIdx.x;
    int warp = tid >> 5, lane = tid & 31;
    int wy = warp >> 1, wx = warp & 1;
    int g = lane >> 2, t4 = lane & 3;
    int m0 = blockIdx.y*128, n0 = blockIdx.x*128;

    int nkt = K >> 4;

    auto issue = [&](int kt) {
        int buf = kt & (TG_STAGES-1);
        float* as = Asm + buf*TG_ATILE;
        float* bs = Bsm + buf*TG_BTILE;
        int row = tid >> 2, seg = (tid & 3)*4;
        const float* a0 = A + (long)(m0 + row)*K + kt*16 + seg;
        cp16(as + row*TG_ASTRIDE + seg, a0);
        cp16(as + (row+64)*TG_ASTRIDE + seg, a0 + (long)64*K);
        int krow = tid >> 5, col = (lane)*4;
        const float* b0 = B + (long)(kt*16 + krow)*N + n0 + col;
        cp16(bs + krow*TG_BSTRIDE + col, b0);
        cp16(bs + (krow+8)*TG_BSTRIDE + col, b0 + (long)8*N);
        asm volatile("cp.async.commit_group;");
    };

    float acc[2][8][4];
    #pragma unroll
    for (int mi = 0; mi < 2; mi++)
        #pragma unroll
        for (int nj = 0; nj < 8; nj++)
            #pragma unroll
            for (int c = 0; c < 4; c++) acc[mi][nj][c] = 0.f;

    #pragma unroll
    for (int s = 0; s < TG_STAGES-1; s++)
        if (s < nkt) issue(s);

    for (int kt = 0; kt < nkt; kt++) {
        asm volatile("cp.async.wait_group %0;" :: "n"(TG_STAGES-2));
        __syncthreads();

        if (kt + TG_STAGES-1 < nkt) issue(kt + TG_STAGES-1);

        int buf = kt & (TG_STAGES-1);
        const float* as = Asm + buf*TG_ATILE;
        const float* bs = Bsm + buf*TG_BTILE;

        #pragma unroll
        for (int ks = 0; ks < 2; ks++) {
            int kk = ks*8;
            unsigned af[2][4], bf[8][2];
            #pragma unroll
            for (int mi = 0; mi < 2; mi++) {
                int mr = wy*32 + mi*16 + g;
                af[mi][0] = f2tf32(as[mr*TG_ASTRIDE + kk + t4]);
                af[mi][1] = f2tf32(as[(mr+8)*TG_ASTRIDE + kk + t4]);
                af[mi][2] = f2tf32(as[mr*TG_ASTRIDE + kk + t4 + 4]);
                af[mi][3] = f2tf32(as[(mr+8)*TG_ASTRIDE + kk + t4 + 4]);
            }
            #pragma unroll
            for (int nj = 0; nj < 8; nj++) {
                int nc = wx*64 + nj*8 + g;
                bf[nj][0] = f2tf32(bs[(kk + t4)*TG_BSTRIDE + nc]);
                bf[nj][1] = f2tf32(bs[(kk + t4 + 4)*TG_BSTRIDE + nc]);
            }
            #pragma unroll
            for (int mi = 0; mi < 2; mi++)
                #pragma unroll
                for (int nj = 0; nj < 8; nj++)
                    mma_tf32(acc[mi][nj], af[mi], bf[nj]);
        }
    }

    #pragma unroll
    for (int mi = 0; mi < 2; mi++) {
        #pragma unroll
        for (int nj = 0; nj < 8; nj++) {
            int row = m0 + wy*32 + mi*16 + g;
            int col = n0 + wx*64 + nj*8 + t4*2;
            float* p0 = &C[(long)row*N + col];
            float* p1 = &C[(long)(row+8)*N + col];
            float2 v0 = make_float2(acc[mi][nj][0], acc[mi][nj][1]);
            float2 v1 = make_float2(acc[mi][nj][2], acc[mi][nj][3]);
            if (accum) {
                float2 o0 = *(float2*)p0, o1 = *(float2*)p1;
                v0.x += o0.x; v0.y += o0.y; v1.x += o1.x; v1.y += o1.y;
            }
            *(float2*)p0 = v0;
            *(float2*)p1 = v1;
        }
    }
}

// ---------------- l2norm + scale: warp per (row,head) ----------------
__global__ void __launch_bounds__(256) norm_heads(const float* __restrict__ src,
        int srcStride, int colOff, int rowOff,
        const float* __restrict__ scale, float* __restrict__ dst, int nrows)
{
    int w = threadIdx.x >> 5, lane = threadIdx.x & 31;
    int pair = blockIdx.x*8 + w;
    int h = pair / nrows;
    int row = pair - h*nrows;
    int d0 = lane*2;

    const float* sp = src + (long)(rowOff+row)*srcStride + colOff + h*HD + d0;
    float2 v = *(const float2*)sp;
    float s = v.x*v.x + v.y*v.y;
    #pragma unroll
    for (int o = 16; o; o >>= 1) s += __shfl_xor_sync(0xffffffffu, s, o);
    float inv = 1.f / fmaxf(sqrtf(s), 1e-12f);
    float2 sc = *(const float2*)(scale + d0);
    float2 r = make_float2(v.x*inv*sc.x, v.y*inv*sc.y);
    *(float2*)(dst + (long)pair*HD + d0) = r;
}

// fused q+k norm from qkv (blockIdx.y: 0=q, 1=k)
__global__ void __launch_bounds__(256) norm_qk(const float* __restrict__ qkv,
        const float* __restrict__ q_scale, const float* __restrict__ k_scale,
        float* __restrict__ qn, float* __restrict__ kn)
{
    int w = threadIdx.x >> 5, lane = threadIdx.x & 31;
    int pair = blockIdx.x*8 + w;
    int h = pair / NSEQ;
    int row = pair - h*NSEQ;
    int d0 = lane*2;
    int colOff = blockIdx.y ? 1024 : 0;
    const float* scale = blockIdx.y ? k_scale : q_scale;
    float* dst = blockIdx.y ? kn : qn;

    const float* sp = qkv + (long)row*3072 + colOff + h*HD + d0;
    float2 v = *(const float2*)sp;
    float s = v.x*v.x + v.y*v.y;
    #pragma unroll
    for (int o = 16; o; o >>= 1) s += __shfl_xor_sync(0xffffffffu, s, o);
    float inv = 1.f / fmaxf(sqrtf(s), 1e-12f);
    float2 sc = *(const float2*)(scale + d0);
    float2 r = make_float2(v.x*inv*sc.x, v.y*inv*sc.y);
    *(float2*)(dst + (long)pair*HD + d0) = r;
}

// ---------------- flash attention: conflict-free pads (Q/P/V=72, K=68) ----------------
#define QPAD 72
#define KPAD 68
#define TQ (64*QPAD)
#define TK (64*KPAD)
#define FLASH_SMEM ((5*TQ + TK)*4 + 256*4)

__global__ void __launch_bounds__(256, 2) flashmma(
        const float* __restrict__ Q, int qHeadRows,
        const float* __restrict__ Kh, int kHeadRows,
        const float* __restrict__ Vall, long vstride, int vColHeadMul, int vColAdd,
        int vRowExtra,
        const float* __restrict__ bias,
        float* __restrict__ Out, long ostride, int oColMul, int oColAdd,
        int L, int nwin)
{
    extern __shared__ unsigned usm[];
    unsigned* QHI = usm;                          // [d][row] pad 72
    unsigned* QLO = usm + TQ;                     // [d][row] pad 72
    float* KR  = (float*)(usm + 2*TQ);            // [key][d] pad 68
    float* VR0 = (float*)(usm + 2*TQ + TK);       // [key][d] pad 72
    float* VR1 = (float*)(usm + 3*TQ + TK);       // [key][d] pad 72
    unsigned* PT = usm + 4*TQ + TK;               // [key][row] pad 72
    float* SMAX = (float*)(usm + 5*TQ + TK);
    float* SSUM = SMAX + 128;

    int tid = threadIdx.x;
    int warp = tid >> 5, lane = tid & 31;
    int wy = warp >> 1, wx = warp & 1;
    int g = lane >> 2, t4 = lane & 3;

    int z = blockIdx.y;
    int h = z / nwin, w = z - h*nwin;
    int winw = qHeadRows / nwin;
    int i0 = blockIdx.x*64;
    int qrow0 = w*winw + i0;
    int kOff = (nwin > 1) ? (w-1)*winw : 0;

    const float* Qblk = Q + ((long)h*qHeadRows + qrow0)*64;
    const float* Kbase = Kh + (long)h*kHeadRows*64;
    const float* Vbase = Vall + vColHeadMul*h + vColAdd;
    const float* biasH = bias ? bias + (long)h*WIDTH*KEYW : nullptr;

    auto issueK = [&](int c0) {
        #pragma unroll
        for (int t = 0; t < 4; t++) {
            int c4 = tid + t*256;
            int key = c4 >> 4, seg = (c4 & 15)*4;
            int kr = kOff + c0 + key;
            cp16p(KR + key*KPAD + seg, Kbase + (long)kr*64 + seg, (kr >= 0) ? 16 : 0);
        }
        asm volatile("cp.async.commit_group;");
    };
    auto issueV = [&](int c0, float* VB) {
        #pragma unroll
        for (int t = 0; t < 4; t++) {
            int c4 = tid + t*256;
            int key = c4 >> 4, seg = (c4 & 15)*4;
            int kr = kOff + c0 + key;
            cp16p(VB + key*QPAD + seg, Vbase + (long)(kr + vRowExtra)*vstride + seg,
                  (kr >= 0) ? 16 : 0);
        }
        asm volatile("cp.async.commit_group;");
    };

    #pragma unroll
    for (int t = 0; t < 16; t++) {
        int e = tid + t*256;
        int r = e >> 6, c = e & 63;
        float v = Qblk[(long)r*64 + c];
        unsigned hi = f2tf32(v);
        QHI[c*QPAD + r] = hi;
        QLO[c*QPAD + r] = f2tf32(v - __uint_as_float(hi));
    }

    int mr = wy*16 + g;
    float m0r = -3.402823466e38f, m1r = -3.402823466e38f;
    float l0 = 0.f, l1 = 0.f;
    float acc[4][4];
    #pragma unroll
    for (int nj = 0; nj < 4; nj++)
        #pragma unroll
        for (int c = 0; c < 4; c++) acc[nj][c] = 0.f;

    int Lq = biasH ? (i0 + 576) : L;
    if (Lq > L) Lq = L;
    int nch = (Lq + 63) >> 6;

    issueV(0, VR0);
    issueK(0);

    for (int ci = 0; ci < nch; ci++) {
        int c0 = ci << 6;
        float* VB = (ci & 1) ? VR1 : VR0;
        bool more = (ci + 1 < nch);

        if (more) {
            issueV(c0 + 64, (ci & 1) ? VR0 : VR1);
            asm volatile("cp.async.wait_group 1;");
        } else {
            asm volatile("cp.async.wait_group 0;");
        }
        __syncthreads();

        float sf[4][4];
        #pragma unroll
        for (int nj = 0; nj < 4; nj++)
            #pragma unroll
            for (int c = 0; c < 4; c++) sf[nj][c] = 0.f;

        #pragma unroll
        for (int kk = 0; kk < 64; kk += 8) {
            unsigned ahi[4], alo[4];
            ahi[0] = QHI[(kk+t4)*QPAD + mr];
            ahi[1] = QHI[(kk+t4)*QPAD + mr + 8];
            ahi[2] = QHI[(kk+t4+4)*QPAD + mr];
            ahi[3] = QHI[(kk+t4+4)*QPAD + mr + 8];
            alo[0] = QLO[(kk+t4)*QPAD + mr];
            alo[1] = QLO[(kk+t4)*QPAD + mr + 8];
            alo[2] = QLO[(kk+t4+4)*QPAD + mr];
            alo[3] = QLO[(kk+t4+4)*QPAD + mr + 8];
            #pragma unroll
            for (int nj = 0; nj < 4; nj++) {
                int nc = wx*32 + nj*8 + g;
                float k0 = KR[nc*KPAD + kk + t4];
                float k1 = KR[nc*KPAD + kk + t4 + 4];
                unsigned bhi[2] = { f2tf32(k0), f2tf32(k1) };
                unsigned blo[2] = { f2tf32(k0 - __uint_as_float(bhi[0])),
                                    f2tf32(k1 - __uint_as_float(bhi[1])) };
                mma_tf32(sf[nj], ahi, bhi);
                mma_tf32(sf[nj], alo, bhi);
                mma_tf32(sf[nj], ahi, blo);
            }
        }

        int ir0 = i0 + mr, ir1 = ir0 + 8;
        #pragma unroll
        for (int nj = 0; nj < 4; nj++) {
            int j0 = c0 + wx*32 + nj*8 + 2*t4;
            #pragma unroll
            for (int c = 0; c < 4; c++) sf[nj][c] *= 8.f;
            if (biasH) {
                float2 b0 = *(const float2*)&biasH[(long)ir0*KEYW + j0];
                float2 b1 = *(const float2*)&biasH[(long)ir1*KEYW + j0];
                sf[nj][0] += b0.x; sf[nj][1] += b0.y;
                sf[nj][2] += b1.x; sf[nj][3] += b1.y;
                if (j0     > ir0 + 512) sf[nj][0] = -3.402823466e38f;
                if (j0 + 1 > ir0 + 512) sf[nj][1] = -3.402823466e38f;
                if (j0     > ir1 + 512) sf[nj][2] = -3.402823466e38f;
                if (j0 + 1 > ir1 + 512) sf[nj][3] = -3.402823466e38f;
            }
        }

        float pm0 = -3.402823466e38f, pm1 = -3.402823466e38f;
        #pragma unroll
        for (int nj = 0; nj < 4; nj++) {
            pm0 = fmaxf(pm0, fmaxf(sf[nj][0], sf[nj][1]));
            pm1 = fmaxf(pm1, fmaxf(sf[nj][2], sf[nj][3]));
        }
        pm0 = fmaxf(pm0, __shfl_xor_sync(0xffffffffu, pm0, 1));
        pm0 = fmaxf(pm0, __shfl_xor_sync(0xffffffffu, pm0, 2));
        pm1 = fmaxf(pm1, __shfl_xor_sync(0xffffffffu, pm1, 1));
        pm1 = fmaxf(pm1, __shfl_xor_sync(0xffffffffu, pm1, 2));
        if (t4 == 0) {
            SMAX[mr*2 + wx] = pm0;
            SMAX[(mr+8)*2 + wx] = pm1;
        }
        __syncthreads();

        if (more) issueK(c0 + 64);

        float cmax0 = fmaxf(SMAX[mr*2], SMAX[mr*2+1]);
        float cmax1 = fmaxf(SMAX[(mr+8)*2], SMAX[(mr+8)*2+1]);

        float mn0 = fmaxf(m0r, cmax0);
        float mn1 = fmaxf(m1r, cmax1);
        float corr0 = __expf(m0r - mn0);
        float corr1 = __expf(m1r - mn1);
        m0r = mn0; m1r = mn1;

        float ps0 = 0.f, ps1 = 0.f;
        #pragma unroll
        for (int nj = 0; nj < 4; nj++) {
            int j0 = wx*32 + nj*8 + 2*t4;
            float p00 = __expf(sf[nj][0] - mn0);
            float p01 = __expf(sf[nj][1] - mn0);
            float p10 = __expf(sf[nj][2] - mn1);
            float p11 = __expf(sf[nj][3] - mn1);
            ps0 += p00 + p01;
            ps1 += p10 + p11;
            PT[j0*QPAD + mr]       = f2tf32(p00);
            PT[(j0+1)*QPAD + mr]   = f2tf32(p01);
            PT[j0*QPAD + mr+8]     = f2tf32(p10);
            PT[(j0+1)*QPAD + mr+8] = f2tf32(p11);
        }
        ps0 += __shfl_xor_sync(0xffffffffu, ps0, 1);
        ps0 += __shfl_xor_sync(0xffffffffu, ps0, 2);
        ps1 += __shfl_xor_sync(0xffffffffu, ps1, 1);
        ps1 += __shfl_xor_sync(0xffffffffu, ps1, 2);
        if (t4 == 0) {
            SSUM[mr*2 + wx] = ps0;
            SSUM[(mr+8)*2 + wx] = ps1;
        }

        #pragma unroll
        for (int nj = 0; nj < 4; nj++) {
            acc[nj][0] *= corr0; acc[nj][1] *= corr0;
            acc[nj][2] *= corr1; acc[nj][3] *= corr1;
        }
        __syncthreads();

        l0 = l0*corr0 + SSUM[mr*2] + SSUM[mr*2+1];
        l1 = l1*corr1 + SSUM[(mr+8)*2] + SSUM[(mr+8)*2+1];

        #pragma unroll
        for (int kk = 0; kk < 64; kk += 8) {
            unsigned ap[4];
            ap[0] = PT[(kk+t4)*QPAD + mr];
            ap[1] = PT[(kk+t4)*QPAD + mr + 8];
            ap[2] = PT[(kk+t4+4)*QPAD + mr];
            ap[3] = PT[(kk+t4+4)*QPAD + mr + 8];
            #pragma unroll
            for (int nj = 0; nj < 4; nj++) {
                int nc = wx*32 + nj*8 + g;
                unsigned bv[2] = { f2tf32(VB[(kk+t4)*QPAD + nc]),
                                   f2tf32(VB[(kk+t4+4)*QPAD + nc]) };
                mma_tf32(acc[nj], ap, bv);
            }
        }
        __syncthreads();
    }

    float inv0 = 1.f / l0, inv1 = 1.f / l1;
    #pragma unroll
    for (int nj = 0; nj < 4; nj++) {
        int col = h*oColMul + oColAdd + wx*32 + nj*8 + 2*t4;
        long r0 = (long)(qrow0 + mr)*ostride + col;
        long r1 = (long)(qrow0 + mr + 8)*ostride + col;
        *(float2*)&Out[r0] = make_float2(acc[nj][0]*inv0, acc[nj][1]*inv0);
        *(float2*)&Out[r1] = make_float2(acc[nj][2]*inv1, acc[nj][3]*inv1);
    }
}

// ---------------- memories copy ----------------
__global__ void memories_kernel(const float* __restrict__ qkv, float* __restrict__ out)
{
    int idx = blockIdx.x*256 + threadIdx.x;
    if (idx >= 2*HEADS*WIDTH*HD) return;
    int d = idx & 63;
    int i = (idx >> 6) & 511;
    int h = (idx >> 15) & 15;
    int s = idx >> 19;
    out[idx] = qkv[(long)(3584+i)*3072 + (s ? 2048 : 1024) + h*HD + d];
}

// ---------------- new_states ----------------
__global__ void newstates_kernel(const float* __restrict__ gz, const float* __restrict__ bg,
        const float* __restrict__ beta, const float* __restrict__ init_state,
        float* __restrict__ out)
{
    int idx = blockIdx.x*256 + threadIdx.x;
    if (idx >= NST*DIMM) return;
    int c = idx & (DIMM-1);
    float sig = 1.f/(1.f+expf(-beta[c]));
    float z = gz[idx] + bg[c];
    out[idx] = sig*z + (1.f-sig)*init_state[idx];
}

// ---------------- host launch ----------------
static float* symaddr(const void* s)
{
    void* p = nullptr;
    cudaGetSymbolAddress(&p, s);
    return (float*)p;
}

extern "C" void kernel_launch(void* const* d_in, const int* in_sizes, int n_in,
                              void* d_out, int out_size)
{
    const float* x       = (const float*)d_in[0];
    const float* bias    = (const float*)d_in[1];
    const float* gamma   = (const float*)d_in[2];
    const float* w_qkv   = (const float*)d_in[3];
    const float* q_scale = (const float*)d_in[4];
    const float* k_scale = (const float*)d_in[5];
    const float* w_out   = (const float*)d_in[6];
    const float* s_gamma = (const float*)d_in[7];
    const float* w_q2s   = (const float*)d_in[8];
    const float* w_qfs   = (const float*)d_in[9];
    const float* w_sqkv  = (const float*)d_in[10];
    const float* init_st = (const float*)d_in[11];
    const float* pos_ids = (const float*)d_in[12];
    const float* w_sout  = (const float*)d_in[13];
    const float* ts_q    = (const float*)d_in[14];
    const float* ts_k    = (const float*)d_in[15];
    const float* ss_q    = (const float*)d_in[16];
    const float* ss_k    = (const float*)d_in[17];
    const float* fs_q    = (const float*)d_in[18];
    const float* fs_k    = (const float*)d_in[19];
    const float* w_gate  = (const float*)d_in[20];
    const float* b_gate  = (const float*)d_in[21];
    const float* beta    = (const float*)d_in[22];
    float* out = (float*)d_out;

    float* xn   = symaddr(g_xn);
    float* qkv  = symaddr(g_qkv);
    float* q2s  = symaddr(g_q2s);
    float* sqkv = symaddr(g_state_qkv);
    float* st   = symaddr(g_st);
    float* qfsr = symaddr(g_qfs_raw);
    float* qnm  = symaddr(g_qn_main);
    float* knm  = symaddr(g_kn_main);
    float* qnts = symaddr(g_qn_ts);
    float* knts = symaddr(g_kn_ts);
    float* qnss = symaddr(g_qn_ss);
    float* knss = symaddr(g_kn_ss);
    float* qnfs = symaddr(g_qn_fs);
    float* knfs = symaddr(g_kn_fs);
    float* cat  = symaddr(g_cat);
    float* scat = symaddr(g_state_cat);
    float* so   = symaddr(g_so);
    float* zb   = symaddr(g_z);

    static cudaStream_t s1 = nullptr;
    static cudaEvent_t evXn, evQn, evTs, evS1;
    if (!s1) {
        cudaStreamCreateWithFlags(&s1, cudaStreamNonBlocking);
        cudaEventCreateWithFlags(&evXn, cudaEventDisableTiming);
        cudaEventCreateWithFlags(&evQn, cudaEventDisableTiming);
        cudaEventCreateWithFlags(&evTs, cudaEventDisableTiming);
        cudaEventCreateWithFlags(&evS1, cudaEventDisableTiming);
        cudaFuncSetAttribute(flashmma, cudaFuncAttributeMaxDynamicSharedMemorySize, FLASH_SMEM);
        cudaFuncSetAttribute(tgemm, cudaFuncAttributeMaxDynamicSharedMemorySize, TGEMM_SMEM);
    }

    cudaStream_t s0 = 0;

    // ===== stream0: main path =====
    ln_kernel<<<NSEQ, 256, 0, s0>>>(x, gamma, nullptr, xn);
    cudaEventRecord(evXn, s0);

    tgemm<<<dim3(3072/128, NSEQ/128), 256, TGEMM_SMEM, s0>>>(xn, w_qkv, qkv, NSEQ, 3072, DIMM, 0);
    norm_qk<<<dim3(NSEQ*HEADS/8, 2), 256, 0, s0>>>(qkv, q_scale, k_scale, qnm, knm);
    norm_heads<<<NST*HEADS/8, 256, 0, s0>>>(qkv, 3072, 1024, 3584, fs_k, knfs, NST);
    cudaEventRecord(evQn, s0);

    flashmma<<<dim3(WIDTH/64, HEADS*NW), 256, FLASH_SMEM, s0>>>(
        qnm, NSEQ, knm, NSEQ, qkv, 3072, HD, 2048, 0, bias,
        cat, 2*DIMM, HD, 0, KEYW, NW);

    // ===== stream1: state branch =====
    cudaStreamWaitEvent(s1, evXn, 0);
    ln_kernel<<<NST, 256, 0, s1>>>(init_st, s_gamma, pos_ids, st);
    tgemm<<<dim3(3072/128, NST/128), 256, TGEMM_SMEM, s1>>>(init_st, w_sqkv, sqkv, NST, 3072, DIMM, 0);
    tgemm<<<dim3(DIMM/128, NST/128), 256, TGEMM_SMEM, s1>>>(st, w_qfs, qfsr, NST, DIMM, DIMM, 0);
    tgemm<<<dim3(DIMM/128, NSEQ/128), 256, TGEMM_SMEM, s1>>>(xn, w_q2s, q2s, NSEQ, DIMM, DIMM, 0);

    norm_heads<<<NSEQ*HEADS/8, 256, 0, s1>>>(q2s, 1024, 0,    0, ts_q, qnts, NSEQ);
    norm_heads<<<NST*HEADS/8,  256, 0, s1>>>(sqkv, 3072, 1024, 0, ts_k, knts, NST);
    norm_heads<<<NST*HEADS/8,  256, 0, s1>>>(sqkv, 3072, 0,    0, ss_q, qnss, NST);
    norm_heads<<<NST*HEADS/8,  256, 0, s1>>>(sqkv, 3072, 1024, 0, ss_k, knss, NST);
    norm_heads<<<NST*HEADS/8,  256, 0, s1>>>(qfsr, 1024, 0,    0, fs_q, qnfs, NST);

    flashmma<<<dim3(NSEQ/64, HEADS), 256, FLASH_SMEM, s1>>>(
        qnts, NSEQ, knts, NST, sqkv, 3072, HD, 2048, 0, nullptr,
        cat, 2*DIMM, HD, DIMM, NST, 1);
    cudaEventRecord(evTs, s1);

    flashmma<<<dim3(NST/64, HEADS), 256, FLASH_SMEM, s1>>>(
        qnss, NST, knss, NST, sqkv, 3072, HD, 2048, 0, nullptr,
        scat, 2*DIMM, 2*HD, 0, NST, 1);

    cudaStreamWaitEvent(s1, evQn, 0);
    flashmma<<<dim3(NST/64, HEADS), 256, FLASH_SMEM, s1>>>(
        qnfs, NST, knfs, NST, qkv, 3072, HD, 2048, 3584, nullptr,
        scat, 2*DIMM, 2*HD, HD, NST, 1);
    memories_kernel<<<(2*HEADS*WIDTH*HD)/256, 256, 0, s1>>>(qkv, out + (long)NSEQ*DIMM);

    tgemm<<<dim3(DIMM/128, NST/128), 256, TGEMM_SMEM, s1>>>(scat, w_sout, so, NST, DIMM, 2*DIMM, 0);
    tgemm<<<dim3(DIMM/128, NST/128), 256, TGEMM_SMEM, s1>>>(so, w_gate, zb, NST, DIMM, DIMM, 0);
    newstates_kernel<<<(NST*DIMM)/256, 256, 0, s1>>>(zb, b_gate, beta, init_st,
            out + (long)NSEQ*DIMM + 2*HEADS*WIDTH*HD);
    cudaEventRecord(evS1, s1);

    // ===== stream0: output projection =====
    cudaStreamWaitEvent(s0, evTs, 0);
    tgemm<<<dim3(DIMM/128, NSEQ/128), 256, TGEMM_SMEM, s0>>>(cat, w_out, out, NSEQ, DIMM, 2*DIMM, 0);

    cudaStreamWaitEvent(s0, evS1, 0);
}

// round 17
// speedup vs baseline: 1.1170x; 1.0448x over previous
#include <cuda_runtime.h>
#include <math.h>

#define NSEQ  4096
#define DIMM  1024
#define HEADS 16
#define HD    64
#define WIDTH 512
#define NW    8
#define NST   512
#define KEYW  1024

// ---------------- scratch ----------------
__device__ float g_xn[NSEQ*DIMM];
__device__ float g_qkv[NSEQ*3*DIMM];
__device__ float g_q2s[NSEQ*DIMM];
__device__ float g_state_qkv[NST*3*DIMM];
__device__ float g_st[NST*DIMM];
__device__ float g_qfs_raw[NST*DIMM];

__device__ float g_qn_main[HEADS*NSEQ*HD];
__device__ float g_kn_main[HEADS*NSEQ*HD];
__device__ float g_qn_ts[HEADS*NSEQ*HD];
__device__ float g_kn_ts[HEADS*NST*HD];
__device__ float g_qn_ss[HEADS*NST*HD];
__device__ float g_kn_ss[HEADS*NST*HD];
__device__ float g_qn_fs[HEADS*NST*HD];
__device__ float g_kn_fs[HEADS*NST*HD];

__device__ float g_cat[NSEQ*2*DIMM];
__device__ float g_state_cat[NST*2*DIMM];
__device__ float g_so[NST*DIMM];
__device__ float g_z[NST*DIMM];

// ---------------- layernorm ----------------
__global__ void __launch_bounds__(256) ln_kernel(const float* __restrict__ x,
        const float* __restrict__ gamma, const float* __restrict__ pos,
        float* __restrict__ out)
{
    int row = blockIdx.x;
    const float* xr = x + (long)row*DIMM;
    float* orow = out + (long)row*DIMM;
    __shared__ float red[256];
    float s = 0.f, s2 = 0.f;
    for (int i = threadIdx.x; i < DIMM; i += 256) { float v = xr[i]; s += v; s2 += v*v; }
    red[threadIdx.x] = s; __syncthreads();
    for (int o = 128; o; o >>= 1) { if (threadIdx.x < o) red[threadIdx.x] += red[threadIdx.x+o]; __syncthreads(); }
    float mu = red[0] * (1.f/DIMM);
    __syncthreads();
    red[threadIdx.x] = s2; __syncthreads();
    for (int o = 128; o; o >>= 1) { if (threadIdx.x < o) red[threadIdx.x] += red[threadIdx.x+o]; __syncthreads(); }
    float var = red[0] * (1.f/DIMM) - mu*mu;
    float inv = rsqrtf(var + 1e-5f);
    for (int i = threadIdx.x; i < DIMM; i += 256) {
        float v = (xr[i]-mu)*inv*gamma[i];
        if (pos) v += pos[(long)row*DIMM + i];
        orow[i] = v;
    }
}

// ---------------- TF32 helpers ----------------
__device__ __forceinline__ unsigned f2tf32(float f)
{
    unsigned r;
    asm("cvt.rna.tf32.f32 %0, %1;" : "=r"(r) : "f"(f));
    return r;
}

__device__ __forceinline__ void mma_tf32(float c[4], const unsigned a[4], const unsigned b[2])
{
    asm volatile(
        "mma.sync.aligned.m16n8k8.row.col.f32.tf32.tf32.f32 "
        "{%0,%1,%2,%3}, {%4,%5,%6,%7}, {%8,%9}, {%0,%1,%2,%3};"
        : "+f"(c[0]), "+f"(c[1]), "+f"(c[2]), "+f"(c[3])
        : "r"(a[0]), "r"(a[1]), "r"(a[2]), "r"(a[3]), "r"(b[0]), "r"(b[1]));
}

__device__ __forceinline__ void cp16(float* dst, const float* src)
{
    unsigned d = (unsigned)__cvta_generic_to_shared(dst);
    asm volatile("cp.async.cg.shared.global [%0], [%1], 16;" :: "r"(d), "l"(src));
}

__device__ __forceinline__ void cp16p(float* dst, const float* src, int sz)
{
    unsigned d = (unsigned)__cvta_generic_to_shared(dst);
    asm volatile("cp.async.cg.shared.global [%0], [%1], 16, %2;" :: "r"(d), "l"(src), "r"(sz));
}

// ---------------- TF32 GEMM: cp.async 4-stage pipeline, conflict-free B ----------------
#define TG_STAGES 4
#define TG_ASTRIDE 20
#define TG_BSTRIDE 136
#define TG_ATILE (128*TG_ASTRIDE)
#define TG_BTILE (16*TG_BSTRIDE)
#define TGEMM_SMEM (TG_STAGES*(TG_ATILE + TG_BTILE)*4)

__global__ void __launch_bounds__(256) tgemm(const float* __restrict__ A,
        const float* __restrict__ B, float* __restrict__ C,
        int M, int N, int K, int accum)
{
    extern __shared__ float tsm[];
    float* Asm = tsm;
    float* Bsm = tsm + TG_STAGES*TG_ATILE;

    int tid = threadIdx.x;
    int warp = tid >> 5, lane = tid & 31;
    int wy = warp >> 1, wx = warp & 1;
    int g = lane >> 2, t4 = lane & 3;
    int m0 = blockIdx.y*128, n0 = blockIdx.x*128;

    int nkt = K >> 4;

    auto issue = [&](int kt) {
        int buf = kt & (TG_STAGES-1);
        float* as = Asm + buf*TG_ATILE;
        float* bs = Bsm + buf*TG_BTILE;
        int row = tid >> 2, seg = (tid & 3)*4;
        const float* a0 = A + (long)(m0 + row)*K + kt*16 + seg;
        cp16(as + row*TG_ASTRIDE + seg, a0);
        cp16(as + (row+64)*TG_ASTRIDE + seg, a0 + (long)64*K);
        int krow = tid >> 5, col = (lane)*4;
        const float* b0 = B + (long)(kt*16 + krow)*N + n0 + col;
        cp16(bs + krow*TG_BSTRIDE + col, b0);
        cp16(bs + (krow+8)*TG_BSTRIDE + col, b0 + (long)8*N);
        asm volatile("cp.async.commit_group;");
    };

    float acc[2][8][4];
    #pragma unroll
    for (int mi = 0; mi < 2; mi++)
        #pragma unroll
        for (int nj = 0; nj < 8; nj++)
            #pragma unroll
            for (int c = 0; c < 4; c++) acc[mi][nj][c] = 0.f;

    #pragma unroll
    for (int s = 0; s < TG_STAGES-1; s++)
        if (s < nkt) issue(s);

    for (int kt = 0; kt < nkt; kt++) {
        asm volatile("cp.async.wait_group %0;" :: "n"(TG_STAGES-2));
        __syncthreads();

        if (kt + TG_STAGES-1 < nkt) issue(kt + TG_STAGES-1);

        int buf = kt & (TG_STAGES-1);
        const float* as = Asm + buf*TG_ATILE;
        const float* bs = Bsm + buf*TG_BTILE;

        #pragma unroll
        for (int ks = 0; ks < 2; ks++) {
            int kk = ks*8;
            unsigned af[2][4], bf[8][2];
            #pragma unroll
            for (int mi = 0; mi < 2; mi++) {
                int mr = wy*32 + mi*16 + g;
                af[mi][0] = f2tf32(as[mr*TG_ASTRIDE + kk + t4]);
                af[mi][1] = f2tf32(as[(mr+8)*TG_ASTRIDE + kk + t4]);
                af[mi][2] = f2tf32(as[mr*TG_ASTRIDE + kk + t4 + 4]);
                af[mi][3] = f2tf32(as[(mr+8)*TG_ASTRIDE + kk + t4 + 4]);
            }
            #pragma unroll
            for (int nj = 0; nj < 8; nj++) {
                int nc = wx*64 + nj*8 + g;
                bf[nj][0] = f2tf32(bs[(kk + t4)*TG_BSTRIDE + nc]);
                bf[nj][1] = f2tf32(bs[(kk + t4 + 4)*TG_BSTRIDE + nc]);
            }
            #pragma unroll
            for (int mi = 0; mi < 2; mi++)
                #pragma unroll
                for (int nj = 0; nj < 8; nj++)
                    mma_tf32(acc[mi][nj], af[mi], bf[nj]);
        }
    }

    #pragma unroll
    for (int mi = 0; mi < 2; mi++) {
        #pragma unroll
        for (int nj = 0; nj < 8; nj++) {
            int row = m0 + wy*32 + mi*16 + g;
            int col = n0 + wx*64 + nj*8 + t4*2;
            float* p0 = &C[(long)row*N + col];
            float* p1 = &C[(long)(row+8)*N + col];
            float2 v0 = make_float2(acc[mi][nj][0], acc[mi][nj][1]);
            float2 v1 = make_float2(acc[mi][nj][2], acc[mi][nj][3]);
            if (accum) {
                float2 o0 = *(float2*)p0, o1 = *(float2*)p1;
                v0.x += o0.x; v0.y += o0.y; v1.x += o1.x; v1.y += o1.y;
            }
            *(float2*)p0 = v0;
            *(float2*)p1 = v1;
        }
    }
}

// ---------------- l2norm + scale: warp per (row,head) ----------------
__global__ void __launch_bounds__(256) norm_heads(const float* __restrict__ src,
        int srcStride, int colOff, int rowOff,
        const float* __restrict__ scale, float* __restrict__ dst, int nrows)
{
    int w = threadIdx.x >> 5, lane = threadIdx.x & 31;
    int pair = blockIdx.x*8 + w;
    int h = pair / nrows;
    int row = pair - h*nrows;
    int d0 = lane*2;

    const float* sp = src + (long)(rowOff+row)*srcStride + colOff + h*HD + d0;
    float2 v = *(const float2*)sp;
    float s = v.x*v.x + v.y*v.y;
    #pragma unroll
    for (int o = 16; o; o >>= 1) s += __shfl_xor_sync(0xffffffffu, s, o);
    float inv = 1.f / fmaxf(sqrtf(s), 1e-12f);
    float2 sc = *(const float2*)(scale + d0);
    float2 r = make_float2(v.x*inv*sc.x, v.y*inv*sc.y);
    *(float2*)(dst + (long)pair*HD + d0) = r;
}

// fused q+k norm from qkv (blockIdx.y: 0=q, 1=k)
__global__ void __launch_bounds__(256) norm_qk(const float* __restrict__ qkv,
        const float* __restrict__ q_scale, const float* __restrict__ k_scale,
        float* __restrict__ qn, float* __restrict__ kn)
{
    int w = threadIdx.x >> 5, lane = threadIdx.x & 31;
    int pair = blockIdx.x*8 + w;
    int h = pair / NSEQ;
    int row = pair - h*NSEQ;
    int d0 = lane*2;
    int colOff = blockIdx.y ? 1024 : 0;
    const float* scale = blockIdx.y ? k_scale : q_scale;
    float* dst = blockIdx.y ? kn : qn;

    const float* sp = qkv + (long)row*3072 + colOff + h*HD + d0;
    float2 v = *(const float2*)sp;
    float s = v.x*v.x + v.y*v.y;
    #pragma unroll
    for (int o = 16; o; o >>= 1) s += __shfl_xor_sync(0xffffffffu, s, o);
    float inv = 1.f / fmaxf(sqrtf(s), 1e-12f);
    float2 sc = *(const float2*)(scale + d0);
    float2 r = make_float2(v.x*inv*sc.x, v.y*inv*sc.y);
    *(float2*)(dst + (long)pair*HD + d0) = r;
}

// ---------------- flash attention: conflict-free pads, LPT block order ----------------
#define QPAD 72
#define KPAD 68
#define TQ (64*QPAD)
#define TK (64*KPAD)
#define FLASH_SMEM ((5*TQ + TK)*4 + 256*4)

__global__ void __launch_bounds__(256, 2) flashmma(
        const float* __restrict__ Q, int qHeadRows,
        const float* __restrict__ Kh, int kHeadRows,
        const float* __restrict__ Vall, long vstride, int vColHeadMul, int vColAdd,
        int vRowExtra,
        const float* __restrict__ bias,
        float* __restrict__ Out, long ostride, int oColMul, int oColAdd,
        int L, int nwin)
{
    extern __shared__ unsigned usm[];
    unsigned* QHI = usm;
    unsigned* QLO = usm + TQ;
    float* KR  = (float*)(usm + 2*TQ);
    float* VR0 = (float*)(usm + 2*TQ + TK);
    float* VR1 = (float*)(usm + 3*TQ + TK);
    unsigned* PT = usm + 4*TQ + TK;
    float* SMAX = (float*)(usm + 5*TQ + TK);
    float* SSUM = SMAX + 128;

    int tid = threadIdx.x;
    int warp = tid >> 5, lane = tid & 31;
    int wy = warp >> 1, wx = warp & 1;
    int g = lane >> 2, t4 = lane & 3;

    int z = blockIdx.y;
    int h = z / nwin, w = z - h*nwin;
    int winw = qHeadRows / nwin;
    int i0 = (gridDim.x - 1 - blockIdx.x)*64;   // LPT: heaviest causal tiles first
    int qrow0 = w*winw + i0;
    int kOff = (nwin > 1) ? (w-1)*winw : 0;

    const float* Qblk = Q + ((long)h*qHeadRows + qrow0)*64;
    const float* Kbase = Kh + (long)h*kHeadRows*64;
    const float* Vbase = Vall + vColHeadMul*h + vColAdd;
    const float* biasH = bias ? bias + (long)h*WIDTH*KEYW : nullptr;

    auto issueK = [&](int c0) {
        #pragma unroll
        for (int t = 0; t < 4; t++) {
            int c4 = tid + t*256;
            int key = c4 >> 4, seg = (c4 & 15)*4;
            int kr = kOff + c0 + key;
            cp16p(KR + key*KPAD + seg, Kbase + (long)kr*64 + seg, (kr >= 0) ? 16 : 0);
        }
        asm volatile("cp.async.commit_group;");
    };
    auto issueV = [&](int c0, float* VB) {
        #pragma unroll
        for (int t = 0; t < 4; t++) {
            int c4 = tid + t*256;
            int key = c4 >> 4, seg = (c4 & 15)*4;
            int kr = kOff + c0 + key;
            cp16p(VB + key*QPAD + seg, Vbase + (long)(kr + vRowExtra)*vstride + seg,
                  (kr >= 0) ? 16 : 0);
        }
        asm volatile("cp.async.commit_group;");
    };

    #pragma unroll
    for (int t = 0; t < 16; t++) {
        int e = tid + t*256;
        int r = e >> 6, c = e & 63;
        float v = Qblk[(long)r*64 + c];
        unsigned hi = f2tf32(v);
        QHI[c*QPAD + r] = hi;
        QLO[c*QPAD + r] = f2tf32(v - __uint_as_float(hi));
    }

    int mr = wy*16 + g;
    float m0r = -3.402823466e38f, m1r = -3.402823466e38f;
    float l0 = 0.f, l1 = 0.f;
    float acc[4][4];
    #pragma unroll
    for (int nj = 0; nj < 4; nj++)
        #pragma unroll
        for (int c = 0; c < 4; c++) acc[nj][c] = 0.f;

    int Lq = biasH ? (i0 + 576) : L;
    if (Lq > L) Lq = L;
    int nch = (Lq + 63) >> 6;

    issueV(0, VR0);
    issueK(0);

    for (int ci = 0; ci < nch; ci++) {
        int c0 = ci << 6;
        float* VB = (ci & 1) ? VR1 : VR0;
        bool more = (ci + 1 < nch);

        if (more) {
            issueV(c0 + 64, (ci & 1) ? VR0 : VR1);
            asm volatile("cp.async.wait_group 1;");
        } else {
            asm volatile("cp.async.wait_group 0;");
        }
        __syncthreads();

        float sf[4][4];
        #pragma unroll
        for (int nj = 0; nj < 4; nj++)
            #pragma unroll
            for (int c = 0; c < 4; c++) sf[nj][c] = 0.f;

        #pragma unroll
        for (int kk = 0; kk < 64; kk += 8) {
            unsigned ahi[4], alo[4];
            ahi[0] = QHI[(kk+t4)*QPAD + mr];
            ahi[1] = QHI[(kk+t4)*QPAD + mr + 8];
            ahi[2] = QHI[(kk+t4+4)*QPAD + mr];
            ahi[3] = QHI[(kk+t4+4)*QPAD + mr + 8];
            alo[0] = QLO[(kk+t4)*QPAD + mr];
            alo[1] = QLO[(kk+t4)*QPAD + mr + 8];
            alo[2] = QLO[(kk+t4+4)*QPAD + mr];
            alo[3] = QLO[(kk+t4+4)*QPAD + mr + 8];
            #pragma unroll
            for (int nj = 0; nj < 4; nj++) {
                int nc = wx*32 + nj*8 + g;
                float k0 = KR[nc*KPAD + kk + t4];
                float k1 = KR[nc*KPAD + kk + t4 + 4];
                unsigned bhi[2] = { f2tf32(k0), f2tf32(k1) };
                unsigned blo[2] = { f2tf32(k0 - __uint_as_float(bhi[0])),
                                    f2tf32(k1 - __uint_as_float(bhi[1])) };
                mma_tf32(sf[nj], ahi, bhi);
                mma_tf32(sf[nj], alo, bhi);
                mma_tf32(sf[nj], ahi, blo);
            }
        }

        int ir0 = i0 + mr, ir1 = ir0 + 8;
        #pragma unroll
        for (int nj = 0; nj < 4; nj++) {
            int j0 = c0 + wx*32 + nj*8 + 2*t4;
            #pragma unroll
            for (int c = 0; c < 4; c++) sf[nj][c] *= 8.f;
            if (biasH) {
                float2 b0 = *(const float2*)&biasH[(long)ir0*KEYW + j0];
                float2 b1 = *(const float2*)&biasH[(long)ir1*KEYW + j0];
                sf[nj][0] += b0.x; sf[nj][1] += b0.y;
                sf[nj][2] += b1.x; sf[nj][3] += b1.y;
                if (j0     > ir0 + 512) sf[nj][0] = -3.402823466e38f;
                if (j0 + 1 > ir0 + 512) sf[nj][1] = -3.402823466e38f;
                if (j0     > ir1 + 512) sf[nj][2] = -3.402823466e38f;
                if (j0 + 1 > ir1 + 512) sf[nj][3] = -3.402823466e38f;
            }
        }

        float pm0 = -3.402823466e38f, pm1 = -3.402823466e38f;
        #pragma unroll
        for (int nj = 0; nj < 4; nj++) {
            pm0 = fmaxf(pm0, fmaxf(sf[nj][0], sf[nj][1]));
            pm1 = fmaxf(pm1, fmaxf(sf[nj][2], sf[nj][3]));
        }
        pm0 = fmaxf(pm0, __shfl_xor_sync(0xffffffffu, pm0, 1));
        pm0 = fmaxf(pm0, __shfl_xor_sync(0xffffffffu, pm0, 2));
        pm1 = fmaxf(pm1, __shfl_xor_sync(0xffffffffu, pm1, 1));
        pm1 = fmaxf(pm1, __shfl_xor_sync(0xffffffffu, pm1, 2));
        if (t4 == 0) {
            SMAX[mr*2 + wx] = pm0;
            SMAX[(mr+8)*2 + wx] = pm1;
        }
        __syncthreads();

        if (more) issueK(c0 + 64);

        float cmax0 = fmaxf(SMAX[mr*2], SMAX[mr*2+1]);
        float cmax1 = fmaxf(SMAX[(mr+8)*2], SMAX[(mr+8)*2+1]);

        float mn0 = fmaxf(m0r, cmax0);
        float mn1 = fmaxf(m1r, cmax1);
        float corr0 = __expf(m0r - mn0);
        float corr1 = __expf(m1r - mn1);
        m0r = mn0; m1r = mn1;

        float ps0 = 0.f, ps1 = 0.f;
        #pragma unroll
        for (int nj = 0; nj < 4; nj++) {
            int j0 = wx*32 + nj*8 + 2*t4;
            float p00 = __expf(sf[nj][0] - mn0);
            float p01 = __expf(sf[nj][1] - mn0);
            float p10 = __expf(sf[nj][2] - mn1);
            float p11 = __expf(sf[nj][3] - mn1);
            ps0 += p00 + p01;
            ps1 += p10 + p11;
            PT[j0*QPAD + mr]       = f2tf32(p00);
            PT[(j0+1)*QPAD + mr]   = f2tf32(p01);
            PT[j0*QPAD + mr+8]     = f2tf32(p10);
            PT[(j0+1)*QPAD + mr+8] = f2tf32(p11);
        }
        ps0 += __shfl_xor_sync(0xffffffffu, ps0, 1);
        ps0 += __shfl_xor_sync(0xffffffffu, ps0, 2);
        ps1 += __shfl_xor_sync(0xffffffffu, ps1, 1);
        ps1 += __shfl_xor_sync(0xffffffffu, ps1, 2);
        if (t4 == 0) {
            SSUM[mr*2 + wx] = ps0;
            SSUM[(mr+8)*2 + wx] = ps1;
        }

        #pragma unroll
        for (int nj = 0; nj < 4; nj++) {
            acc[nj][0] *= corr0; acc[nj][1] *= corr0;
            acc[nj][2] *= corr1; acc[nj][3] *= corr1;
        }
        __syncthreads();

        l0 = l0*corr0 + SSUM[mr*2] + SSUM[mr*2+1];
        l1 = l1*corr1 + SSUM[(mr+8)*2] + SSUM[(mr+8)*2+1];

        #pragma unroll
        for (int kk = 0; kk < 64; kk += 8) {
            unsigned ap[4];
            ap[0] = PT[(kk+t4)*QPAD + mr];
            ap[1] = PT[(kk+t4)*QPAD + mr + 8];
            ap[2] = PT[(kk+t4+4)*QPAD + mr];
            ap[3] = PT[(kk+t4+4)*QPAD + mr + 8];
            #pragma unroll
            for (int nj = 0; nj < 4; nj++) {
                int nc = wx*32 + nj*8 + g;
                unsigned bv[2] = { f2tf32(VB[(kk+t4)*QPAD + nc]),
                                   f2tf32(VB[(kk+t4+4)*QPAD + nc]) };
                mma_tf32(acc[nj], ap, bv);
            }
        }
        __syncthreads();
    }

    float inv0 = 1.f / l0, inv1 = 1.f / l1;
    #pragma unroll
    for (int nj = 0; nj < 4; nj++) {
        int col = h*oColMul + oColAdd + wx*32 + nj*8 + 2*t4;
        long r0 = (long)(qrow0 + mr)*ostride + col;
        long r1 = (long)(qrow0 + mr + 8)*ostride + col;
        *(float2*)&Out[r0] = make_float2(acc[nj][0]*inv0, acc[nj][1]*inv0);
        *(float2*)&Out[r1] = make_float2(acc[nj][2]*inv1, acc[nj][3]*inv1);
    }
}

// ---------------- memories copy ----------------
__global__ void memories_kernel(const float* __restrict__ qkv, float* __restrict__ out)
{
    int idx = blockIdx.x*256 + threadIdx.x;
    if (idx >= 2*HEADS*WIDTH*HD) return;
    int d = idx & 63;
    int i = (idx >> 6) & 511;
    int h = (idx >> 15) & 15;
    int s = idx >> 19;
    out[idx] = qkv[(long)(3584+i)*3072 + (s ? 2048 : 1024) + h*HD + d];
}

// ---------------- new_states ----------------
__global__ void newstates_kernel(const float* __restrict__ gz, const float* __restrict__ bg,
        const float* __restrict__ beta, const float* __restrict__ init_state,
        float* __restrict__ out)
{
    int idx = blockIdx.x*256 + threadIdx.x;
    if (idx >= NST*DIMM) return;
    int c = idx & (DIMM-1);
    float sig = 1.f/(1.f+expf(-beta[c]));
    float z = gz[idx] + bg[c];
    out[idx] = sig*z + (1.f-sig)*init_state[idx];
}

// ---------------- host launch ----------------
static float* symaddr(const void* s)
{
    void* p = nullptr;
    cudaGetSymbolAddress(&p, s);
    return (float*)p;
}

extern "C" void kernel_launch(void* const* d_in, const int* in_sizes, int n_in,
                              void* d_out, int out_size)
{
    const float* x       = (const float*)d_in[0];
    const float* bias    = (const float*)d_in[1];
    const float* gamma   = (const float*)d_in[2];
    const float* w_qkv   = (const float*)d_in[3];
    const float* q_scale = (const float*)d_in[4];
    const float* k_scale = (const float*)d_in[5];
    const float* w_out   = (const float*)d_in[6];
    const float* s_gamma = (const float*)d_in[7];
    const float* w_q2s   = (const float*)d_in[8];
    const float* w_qfs   = (const float*)d_in[9];
    const float* w_sqkv  = (const float*)d_in[10];
    const float* init_st = (const float*)d_in[11];
    const float* pos_ids = (const float*)d_in[12];
    const float* w_sout  = (const float*)d_in[13];
    const float* ts_q    = (const float*)d_in[14];
    const float* ts_k    = (const float*)d_in[15];
    const float* ss_q    = (const float*)d_in[16];
    const float* ss_k    = (const float*)d_in[17];
    const float* fs_q    = (const float*)d_in[18];
    const float* fs_k    = (const float*)d_in[19];
    const float* w_gate  = (const float*)d_in[20];
    const float* b_gate  = (const float*)d_in[21];
    const float* beta    = (const float*)d_in[22];
    float* out = (float*)d_out;

    float* xn   = symaddr(g_xn);
    float* qkv  = symaddr(g_qkv);
    float* q2s  = symaddr(g_q2s);
    float* sqkv = symaddr(g_state_qkv);
    float* st   = symaddr(g_st);
    float* qfsr = symaddr(g_qfs_raw);
    float* qnm  = symaddr(g_qn_main);
    float* knm  = symaddr(g_kn_main);
    float* qnts = symaddr(g_qn_ts);
    float* knts = symaddr(g_kn_ts);
    float* qnss = symaddr(g_qn_ss);
    float* knss = symaddr(g_kn_ss);
    float* qnfs = symaddr(g_qn_fs);
    float* knfs = symaddr(g_kn_fs);
    float* cat  = symaddr(g_cat);
    float* scat = symaddr(g_state_cat);
    float* so   = symaddr(g_so);
    float* zb   = symaddr(g_z);

    static cudaStream_t s1 = nullptr, s2 = nullptr;
    static cudaEvent_t evXn, evQn, evTs, evS1, evSN, evFS2;
    if (!s1) {
        cudaStreamCreateWithFlags(&s1, cudaStreamNonBlocking);
        cudaStreamCreateWithFlags(&s2, cudaStreamNonBlocking);
        cudaEventCreateWithFlags(&evXn, cudaEventDisableTiming);
        cudaEventCreateWithFlags(&evQn, cudaEventDisableTiming);
        cudaEventCreateWithFlags(&evTs, cudaEventDisableTiming);
        cudaEventCreateWithFlags(&evS1, cudaEventDisableTiming);
        cudaEventCreateWithFlags(&evSN, cudaEventDisableTiming);
        cudaEventCreateWithFlags(&evFS2, cudaEventDisableTiming);
        cudaFuncSetAttribute(flashmma, cudaFuncAttributeMaxDynamicSharedMemorySize, FLASH_SMEM);
        cudaFuncSetAttribute(tgemm, cudaFuncAttributeMaxDynamicSharedMemorySize, TGEMM_SMEM);
    }

    cudaStream_t s0 = 0;

    // ===== stream0: main path =====
    ln_kernel<<<NSEQ, 256, 0, s0>>>(x, gamma, nullptr, xn);
    cudaEventRecord(evXn, s0);

    tgemm<<<dim3(3072/128, NSEQ/128), 256, TGEMM_SMEM, s0>>>(xn, w_qkv, qkv, NSEQ, 3072, DIMM, 0);
    norm_qk<<<dim3(NSEQ*HEADS/8, 2), 256, 0, s0>>>(qkv, q_scale, k_scale, qnm, knm);
    norm_heads<<<NST*HEADS/8, 256, 0, s0>>>(qkv, 3072, 1024, 3584, fs_k, knfs, NST);
    cudaEventRecord(evQn, s0);

    flashmma<<<dim3(WIDTH/64, HEADS*NW), 256, FLASH_SMEM, s0>>>(
        qnm, NSEQ, knm, NSEQ, qkv, 3072, HD, 2048, 0, bias,
        cat, 2*DIMM, HD, 0, KEYW, NW);

    // ===== stream1: state branch =====
    cudaStreamWaitEvent(s1, evXn, 0);
    ln_kernel<<<NST, 256, 0, s1>>>(init_st, s_gamma, pos_ids, st);
    tgemm<<<dim3(3072/128, NST/128), 256, TGEMM_SMEM, s1>>>(init_st, w_sqkv, sqkv, NST, 3072, DIMM, 0);
    tgemm<<<dim3(DIMM/128, NST/128), 256, TGEMM_SMEM, s1>>>(st, w_qfs, qfsr, NST, DIMM, DIMM, 0);
    tgemm<<<dim3(DIMM/128, NSEQ/128), 256, TGEMM_SMEM, s1>>>(xn, w_q2s, q2s, NSEQ, DIMM, DIMM, 0);

    norm_heads<<<NSEQ*HEADS/8, 256, 0, s1>>>(q2s, 1024, 0,    0, ts_q, qnts, NSEQ);
    norm_heads<<<NST*HEADS/8,  256, 0, s1>>>(sqkv, 3072, 1024, 0, ts_k, knts, NST);
    norm_heads<<<NST*HEADS/8,  256, 0, s1>>>(sqkv, 3072, 0,    0, ss_q, qnss, NST);
    norm_heads<<<NST*HEADS/8,  256, 0, s1>>>(sqkv, 3072, 1024, 0, ss_k, knss, NST);
    norm_heads<<<NST*HEADS/8,  256, 0, s1>>>(qfsr, 1024, 0,    0, fs_q, qnfs, NST);
    cudaEventRecord(evSN, s1);

    flashmma<<<dim3(NSEQ/64, HEADS), 256, FLASH_SMEM, s1>>>(
        qnts, NSEQ, knts, NST, sqkv, 3072, HD, 2048, 0, nullptr,
        cat, 2*DIMM, HD, DIMM, NST, 1);
    cudaEventRecord(evTs, s1);

    flashmma<<<dim3(NST/64, HEADS), 256, FLASH_SMEM, s1>>>(
        qnss, NST, knss, NST, sqkv, 3072, HD, 2048, 0, nullptr,
        scat, 2*DIMM, 2*HD, 0, NST, 1);

    // ===== stream2: from_state flash + memories (parallel with ts/ss) =====
    cudaStreamWaitEvent(s2, evSN, 0);
    cudaStreamWaitEvent(s2, evQn, 0);
    flashmma<<<dim3(NST/64, HEADS), 256, FLASH_SMEM, s2>>>(
        qnfs, NST, knfs, NST, qkv, 3072, HD, 2048, 3584, nullptr,
        scat, 2*DIMM, 2*HD, HD, NST, 1);
    memories_kernel<<<(2*HEADS*WIDTH*HD)/256, 256, 0, s2>>>(qkv, out + (long)NSEQ*DIMM);
    cudaEventRecord(evFS2, s2);

    // ===== stream1: state output chain (needs ss on s1 + fs on s2) =====
    cudaStreamWaitEvent(s1, evFS2, 0);
    tgemm<<<dim3(DIMM/128, NST/128), 256, TGEMM_SMEM, s1>>>(scat, w_sout, so, NST, DIMM, 2*DIMM, 0);
    tgemm<<<dim3(DIMM/128, NST/128), 256, TGEMM_SMEM, s1>>>(so, w_gate, zb, NST, DIMM, DIMM, 0);
    newstates_kernel<<<(NST*DIMM)/256, 256, 0, s1>>>(zb, b_gate, beta, init_st,
            out + (long)NSEQ*DIMM + 2*HEADS*WIDTH*HD);
    cudaEventRecord(evS1, s1);

    // ===== stream0: output projection =====
    cudaStreamWaitEvent(s0, evTs, 0);
    tgemm<<<dim3(DIMM/128, NSEQ/128), 256, TGEMM_SMEM, s0>>>(cat, w_out, out, NSEQ, DIMM, 2*DIMM, 0);

    cudaStreamWaitEvent(s0, evS1, 0);
}